// round 11
// baseline (speedup 1.0000x reference)
#include <cuda_runtime.h>
#include <cuda_fp16.h>
#include <math.h>
#include <stdint.h>

#define T_MAX   4096
#define D_MODEL 1024
#define HID     4096
#define NE      8

#define BM   128
#define BN   128
#define BKH  64          // k-halves per mainloop iter (128B per row = full SW128 row)
#define NSTG 3

// ---------------- device scratch (static: no allocations) ----------------
__device__ __half        g_Xh[(size_t)T_MAX * D_MODEL];
__device__ __half        g_W1h[(size_t)(NE + 1) * HID * D_MODEL];
__device__ __half        g_W2h[(size_t)(NE + 1) * D_MODEL * HID];
__device__ __half        g_Hh[(size_t)(NE + 1) * T_MAX * HID];
__device__ float         g_slotbuf[(size_t)2 * T_MAX * D_MODEL];
__device__ float         g_gates[T_MAX * 2];
__device__ int           g_topk [T_MAX * 2];
__device__ int           g_counts[NE];
__device__ int           g_tok   [(NE + 1) * T_MAX];
__device__ float         g_rowgate[(NE + 1) * T_MAX];
__device__ unsigned char g_rowslot[(NE + 1) * T_MAX];

// ---------------- PTX helpers ----------------
__device__ __forceinline__ uint32_t smem_u32(const void* p) {
    uint32_t a;
    asm("{ .reg .u64 t; cvta.to.shared.u64 t, %1; cvt.u32.u64 %0, t; }" : "=r"(a) : "l"(p));
    return a;
}
__device__ __forceinline__ void cpa16(uint32_t dst, const void* src, int zf) {
    asm volatile("cp.async.cg.shared.global [%0], [%1], 16, %2;\n"
                 :: "r"(dst), "l"(src), "r"(zf) : "memory");
}
__device__ __forceinline__ void cpa_commit() {
    asm volatile("cp.async.commit_group;\n" ::: "memory");
}
#define LDSM4(r0, r1, r2, r3, addr) \
    asm volatile("ldmatrix.sync.aligned.m8n8.x4.shared.b16 {%0,%1,%2,%3}, [%4];" \
        : "=r"(r0), "=r"(r1), "=r"(r2), "=r"(r3) : "r"(addr))
#define HMMA16(acc, a, b0, b1) \
    asm volatile("mma.sync.aligned.m16n8k16.row.col.f32.f16.f16.f32 " \
        "{%0,%1,%2,%3}, {%4,%5,%6,%7}, {%8,%9}, {%0,%1,%2,%3};" \
        : "+f"((acc)[0]), "+f"((acc)[1]), "+f"((acc)[2]), "+f"((acc)[3]) \
        : "r"((a)[0]), "r"((a)[1]), "r"((a)[2]), "r"((a)[3]), "r"(b0), "r"(b1))

// per-stage: A 128x128B + B 128x128B = 32KB
#define STG_BYTES 32768
#define SMEM_BYTES (NSTG * STG_BYTES + 512)

// ---------------- prep: fp32 -> fp16 (RNE) ----------------
__global__ void to_half_kernel(uint2* __restrict__ dst, const float4* __restrict__ src, int n4) {
    int stride = gridDim.x * blockDim.x;
    for (int i = blockIdx.x * blockDim.x + threadIdx.x; i < n4; i += stride) {
        float4 v = src[i];
        __half2 lo = __floats2half2_rn(v.x, v.y);
        __half2 hi = __floats2half2_rn(v.z, v.w);
        uint2 o;
        o.x = *(uint32_t*)&lo; o.y = *(uint32_t*)&hi;
        dst[i] = o;
    }
}

// ---------------- gating ----------------
__global__ void gate_kernel(const float* __restrict__ x, const float* __restrict__ gw, int T) {
    int warp = (blockIdx.x * blockDim.x + threadIdx.x) >> 5;
    int lane = threadIdx.x & 31;
    if (warp >= T) return;
    const float* xr = x + (size_t)warp * D_MODEL;
    float logit[NE];
#pragma unroll
    for (int e = 0; e < NE; e++) {
        float s = 0.f;
        for (int k = lane; k < D_MODEL; k += 32)
            s = fmaf(xr[k], gw[e * D_MODEL + k], s);
#pragma unroll
        for (int o = 16; o; o >>= 1) s += __shfl_xor_sync(0xffffffffu, s, o);
        logit[e] = s;
    }
    if (lane == 0) {
        int i0 = 0; float v0 = logit[0];
#pragma unroll
        for (int e = 1; e < NE; e++) if (logit[e] > v0) { v0 = logit[e]; i0 = e; }
        int i1 = -1; float v1 = -1e30f;
#pragma unroll
        for (int e = 0; e < NE; e++) if (e != i0 && logit[e] > v1) { v1 = logit[e]; i1 = e; }
        float e1 = expf(v1 - v0);
        float inv = 1.f / (1.f + e1);
        g_topk [2 * warp] = i0;  g_topk [2 * warp + 1] = i1;
        g_gates[2 * warp] = inv; g_gates[2 * warp + 1] = e1 * inv;
    }
}

// ---------------- routing (deterministic prefix scan) ----------------
__global__ void route_kernel(int T) {
    int e = blockIdx.x, tid = threadIdx.x, lane = tid & 31, wid = tid >> 5;
    if (e == NE) {
        for (int i = tid; i < T; i += blockDim.x) {
            g_tok[i] = i; g_rowgate[i] = 1.f; g_rowslot[i] = 0;
        }
        return;
    }
    __shared__ int wsum[8], wpre[8], s_total;
    int base = 0;
    for (int t0 = 0; t0 < T; t0 += 256) {
        int t = t0 + tid, slot = -1;
        if (t < T) {
            if      (g_topk[2 * t]     == e) slot = 0;
            else if (g_topk[2 * t + 1] == e) slot = 1;
        }
        unsigned m = __ballot_sync(0xffffffffu, slot >= 0);
        int pre = __popc(m & ((1u << lane) - 1u));
        if (lane == 0) wsum[wid] = __popc(m);
        __syncthreads();
        if (tid == 0) {
            int a = 0;
            for (int w = 0; w < 8; w++) { wpre[w] = a; a += wsum[w]; }
            s_total = a;
        }
        __syncthreads();
        if (slot >= 0) {
            int pos = base + wpre[wid] + pre;
            size_t r = (size_t)(e + 1) * T_MAX + pos;
            g_tok[r] = t; g_rowgate[r] = g_gates[2 * t + slot];
            g_rowslot[r] = (unsigned char)slot;
        }
        base += s_total;
        __syncthreads();
    }
    if (tid == 0) g_counts[e] = base;
}

// ---------------- fp16 mma.sync GEMM ----------------
// 128x128 block, 4 warps (2x2) of 64x64, BKH=64 halves/iter (one sync per 64 K),
// 3-stage cp.async pipeline + intra-iter fragment double-buffering.
// smem: classic SW128 rows (128B): off = row*128 + ((atom ^ (row&7))<<4).
// Fragment strides: A mt = 16 rows * 128B = 2048; B np = 16 rows * 128B = 2048.
// STAGE1: H = fp16(silu(X @ W1^T)); STAGE2: Y = H @ W2^T (gated).
template <int STAGE, int OUTMODE>
__global__ void __launch_bounds__(128, 2)
gemm_mma(float* __restrict__ out, int T, int zoff) {
    constexpr int K     = (STAGE == 1) ? D_MODEL : HID;
    constexpr int NITER = K / BKH;

    const int s = blockIdx.z + zoff;
    const int count = (s == 0) ? T : g_counts[s - 1];
    const int m0 = blockIdx.y * BM;
    if (m0 >= count) return;
    const int n0 = blockIdx.x * BN;
    const size_t rowbase = (size_t)s * T_MAX;
    const __half* __restrict__ Bw =
        ((STAGE == 1) ? g_W1h : g_W2h) + (size_t)s * K * ((STAGE == 1) ? HID : D_MODEL);
    const __half* __restrict__ Ah = g_Hh + (rowbase + m0) * (size_t)HID;

    extern __shared__ char smem[];
    const uint32_t smb = smem_u32(smem);
    int* stok = (int*)(smem + NSTG * STG_BYTES);

    const int tid = threadIdx.x;
    if (STAGE == 1) {
        for (int i = tid; i < BM; i += 128) {
            int m = m0 + i;
            stok[i] = (m < count) ? g_tok[rowbase + m] : -1;
        }
        __syncthreads();
    }

    // fill buffer: A 128 rows x 128B + B 128 rows x 128B; 16 cp.async/thread
    auto fill = [&](int it, int buf) {
        const int kt = it * BKH;
        const uint32_t aB = smb + buf * STG_BYTES;
        const uint32_t bB = aB + 16384;
#pragma unroll
        for (int i = 0; i < 8; i++) {
            int cid = i * 128 + tid;
            int m = cid >> 3, c = cid & 7;
            uint32_t off = m * 128 + (((c ^ (m & 7))) << 4);
            const __half* srcA; int zf = 16;
            if (STAGE == 1) {
                int t = stok[m];
                srcA = g_Xh + (size_t)((t < 0) ? 0 : t) * D_MODEL + kt + c * 8;
                if (t < 0) zf = 0;
            } else {
                int mg = m0 + m;
                srcA = Ah + (size_t)((mg < count) ? m : 0) * HID + kt + c * 8;
                if (mg >= count) zf = 0;
            }
            cpa16(aB + off, srcA, zf);
            cpa16(bB + off, Bw + (size_t)(n0 + m) * K + kt + c * 8, 16);
        }
        cpa_commit();
    };

    const int lane = tid & 31, wid = tid >> 5;
    const int g = lane >> 2, t4 = lane & 3;
    const int warpM = (wid & 1) * 64, warpN = (wid >> 1) * 64;

    // per-lane ldmatrix base offsets (mt/np = 0, ks = 0)
    uint32_t aoff, boff;
    {
        int m = warpM + (lane & 15), asel = lane >> 4;
        aoff = m * 128 + ((asel ^ (m & 7)) << 4);
        int n = warpN + ((lane >> 4) << 3) + (lane & 7);
        int bsel = (lane >> 3) & 1;
        boff = 16384 + n * 128 + ((bsel ^ (n & 7)) << 4);
    }

    float acc[4][8][4];
#pragma unroll
    for (int a = 0; a < 4; a++)
#pragma unroll
        for (int b = 0; b < 8; b++)
#pragma unroll
            for (int c = 0; c < 4; c++) acc[a][b][c] = 0.f;

    fill(0, 0);
    fill(1, 1);

    uint32_t af[2][4][4], bf[2][4][4];

    for (int it = 0; it < NITER; it++) {
        const int buf = it % NSTG;
        asm volatile("cp.async.wait_group 1;" ::: "memory");
        __syncthreads();
        if (it + 2 < NITER) fill(it + 2, (it + 2) % NSTG);

        const uint32_t Ab = smb + buf * STG_BYTES + aoff;
        const uint32_t Bb = smb + buf * STG_BYTES + boff;

        // prefetch ks=0 fragments
#pragma unroll
        for (int mt = 0; mt < 4; mt++)
            LDSM4(af[0][mt][0], af[0][mt][1], af[0][mt][2], af[0][mt][3], Ab + mt * 2048);
#pragma unroll
        for (int np = 0; np < 4; np++)
            LDSM4(bf[0][np][0], bf[0][np][1], bf[0][np][2], bf[0][np][3], Bb + np * 2048);

#pragma unroll
        for (int ks = 0; ks < 4; ks++) {
            const int cur = ks & 1, nxt = cur ^ 1;
            if (ks < 3) {   // prefetch next ks while computing current
                uint32_t xo = (ks + 1) * 32;
#pragma unroll
                for (int mt = 0; mt < 4; mt++)
                    LDSM4(af[nxt][mt][0], af[nxt][mt][1], af[nxt][mt][2], af[nxt][mt][3],
                          (Ab + mt * 2048) ^ xo);
#pragma unroll
                for (int np = 0; np < 4; np++)
                    LDSM4(bf[nxt][np][0], bf[nxt][np][1], bf[nxt][np][2], bf[nxt][np][3],
                          (Bb + np * 2048) ^ xo);
            }
#pragma unroll
            for (int mt = 0; mt < 4; mt++)
#pragma unroll
                for (int nt = 0; nt < 8; nt++)
                    HMMA16(acc[mt][nt], af[cur][mt],
                           bf[cur][nt >> 1][(nt & 1) * 2],
                           bf[cur][nt >> 1][(nt & 1) * 2 + 1]);
        }
    }

    // ---- epilogue: c0,c1 -> (row g, cols 2t4,2t4+1); c2,c3 -> row g+8
#pragma unroll
    for (int mt = 0; mt < 4; mt++) {
#pragma unroll
        for (int half = 0; half < 2; half++) {
            int m = m0 + warpM + mt * 16 + g + half * 8;
            if (m >= count) continue;
            size_t r = rowbase + m;
            if (STAGE == 1) {
                __half* hp = g_Hh + r * (size_t)HID + n0 + warpN + 2 * t4;
#pragma unroll
                for (int nt = 0; nt < 8; nt++) {
                    float v0 = acc[mt][nt][half * 2 + 0];
                    float v1 = acc[mt][nt][half * 2 + 1];
                    v0 = v0 / (1.f + __expf(-v0));
                    v1 = v1 / (1.f + __expf(-v1));
                    *(__half2*)(hp + nt * 8) = __floats2half2_rn(v0, v1);
                }
            } else {
                int   t  = g_tok[r];
                float gv = g_rowgate[r];
                float* op;
                if (OUTMODE == 0)
                    op = out + (size_t)t * D_MODEL + n0 + warpN + 2 * t4;
                else {
                    int sl = g_rowslot[r];
                    op = g_slotbuf + ((size_t)sl * T_MAX + (size_t)t) * D_MODEL
                       + n0 + warpN + 2 * t4;
                }
#pragma unroll
                for (int nt = 0; nt < 8; nt++)
                    *(float2*)(op + nt * 8) =
                        make_float2(gv * acc[mt][nt][half * 2 + 0],
                                    gv * acc[mt][nt][half * 2 + 1]);
            }
        }
    }
}

// ---------------- combine ----------------
__global__ void combine_kernel(float* __restrict__ out, int T) {
    size_t n = (size_t)T * D_MODEL;
    size_t stride = (size_t)gridDim.x * blockDim.x;
    for (size_t i = (size_t)blockIdx.x * blockDim.x + threadIdx.x; i < n; i += stride)
        out[i] += g_slotbuf[i] + g_slotbuf[(size_t)T_MAX * D_MODEL + i];
}

// ---------------- launch ----------------
extern "C" void kernel_launch(void* const* d_in, const int* in_sizes, int n_in,
                              void* d_out, int out_size) {
    const float* x   = (const float*)d_in[0];
    const float* sw1 = (const float*)d_in[1];
    const float* sw2 = (const float*)d_in[2];
    const float* ew1 = (const float*)d_in[3];
    const float* ew2 = (const float*)d_in[4];
    const float* gw  = (const float*)d_in[5];
    float* out = (float*)d_out;
    int T = in_sizes[0] / D_MODEL;

    cudaFuncSetAttribute(gemm_mma<1, 0>, cudaFuncAttributeMaxDynamicSharedMemorySize, SMEM_BYTES);
    cudaFuncSetAttribute(gemm_mma<2, 0>, cudaFuncAttributeMaxDynamicSharedMemorySize, SMEM_BYTES);
    cudaFuncSetAttribute(gemm_mma<2, 1>, cudaFuncAttributeMaxDynamicSharedMemorySize, SMEM_BYTES);

    __half *d_Xh, *d_W1h, *d_W2h;
    cudaGetSymbolAddress((void**)&d_Xh, g_Xh);
    cudaGetSymbolAddress((void**)&d_W1h, g_W1h);
    cudaGetSymbolAddress((void**)&d_W2h, g_W2h);

    // fp32 -> fp16 RNE conversion; big grids to expose MLP
    to_half_kernel<<<2048, 256>>>((uint2*)d_Xh, (const float4*)x, T * D_MODEL / 4);
    to_half_kernel<<<2048, 256>>>((uint2*)d_W1h, (const float4*)sw1, HID * D_MODEL / 4);
    to_half_kernel<<<16384, 256>>>((uint2*)(d_W1h + (size_t)HID * D_MODEL),
                                   (const float4*)ew1, NE * HID * D_MODEL / 4);
    to_half_kernel<<<2048, 256>>>((uint2*)d_W2h, (const float4*)sw2, D_MODEL * HID / 4);
    to_half_kernel<<<16384, 256>>>((uint2*)(d_W2h + (size_t)D_MODEL * HID),
                                   (const float4*)ew2, NE * D_MODEL * HID / 4);

    gate_kernel<<<(T + 7) / 8, 256>>>(x, gw, T);
    route_kernel<<<NE + 1, 256>>>(T);

    {   // stage 1: all 9 segments (empty m-tiles early-exit)
        dim3 g(HID / BN, T_MAX / BM, NE + 1);
        gemm_mma<1, 0><<<g, 128, SMEM_BYTES>>>(nullptr, T, 0);
    }
    {   // stage 2 shared -> out ('=' writes every element)
        dim3 g(D_MODEL / BN, T_MAX / BM, 1);
        gemm_mma<2, 0><<<g, 128, SMEM_BYTES>>>(out, T, 0);
    }
    {   // stage 2 experts -> per-slot buffers (race-free)
        dim3 g(D_MODEL / BN, T_MAX / BM, NE);
        gemm_mma<2, 1><<<g, 128, SMEM_BYTES>>>(nullptr, T, 1);
    }
    combine_kernel<<<1024, 256>>>(out, T);
}

// round 12
// speedup vs baseline: 1.5342x; 1.5342x over previous
#include <cuda_runtime.h>
#include <cuda_fp16.h>
#include <math.h>
#include <stdint.h>

#define T_MAX   4096
#define D_MODEL 1024
#define HID     4096
#define NE      8

#define BM   128
#define BN   128
#define BKH  32          // k-halves per mainloop iter (64B per row)
#define NSTG 3

// ---------------- device scratch (static: no allocations) ----------------
__device__ __half        g_Xh[(size_t)T_MAX * D_MODEL];
__device__ __half        g_W1h[(size_t)(NE + 1) * HID * D_MODEL];
__device__ __half        g_W2h[(size_t)(NE + 1) * D_MODEL * HID];
__device__ __half        g_Hh[(size_t)(NE + 1) * T_MAX * HID];
__device__ float         g_slotbuf[(size_t)2 * T_MAX * D_MODEL];
__device__ float         g_gates[T_MAX * 2];
__device__ int           g_topk [T_MAX * 2];
__device__ int           g_counts[NE];
__device__ int           g_tok   [(NE + 1) * T_MAX];
__device__ float         g_rowgate[(NE + 1) * T_MAX];
__device__ unsigned char g_rowslot[(NE + 1) * T_MAX];

// ---------------- PTX helpers ----------------
__device__ __forceinline__ uint32_t smem_u32(const void* p) {
    uint32_t a;
    asm("{ .reg .u64 t; cvta.to.shared.u64 t, %1; cvt.u32.u64 %0, t; }" : "=r"(a) : "l"(p));
    return a;
}
__device__ __forceinline__ void cpa16(uint32_t dst, const void* src, int zf) {
    asm volatile("cp.async.cg.shared.global [%0], [%1], 16, %2;\n"
                 :: "r"(dst), "l"(src), "r"(zf) : "memory");
}
__device__ __forceinline__ void cpa_commit() {
    asm volatile("cp.async.commit_group;\n" ::: "memory");
}
#define LDSM4(r0, r1, r2, r3, addr) \
    asm volatile("ldmatrix.sync.aligned.m8n8.x4.shared.b16 {%0,%1,%2,%3}, [%4];" \
        : "=r"(r0), "=r"(r1), "=r"(r2), "=r"(r3) : "r"(addr))

// per-stage: A 8KB + B 8KB
#define STG_BYTES 16384
#define SMEM_BYTES (NSTG * STG_BYTES + 512)

// ---------------- prep: fp32 -> fp16 (RNE), 32B read / 16B write per iter ----
__global__ void to_half_kernel(uint4* __restrict__ dst, const float4* __restrict__ src, int n8) {
    int stride = gridDim.x * blockDim.x;
    for (int i = blockIdx.x * blockDim.x + threadIdx.x; i < n8; i += stride) {
        float4 v0 = src[2 * i + 0];
        float4 v1 = src[2 * i + 1];
        __half2 a = __floats2half2_rn(v0.x, v0.y);
        __half2 b = __floats2half2_rn(v0.z, v0.w);
        __half2 c = __floats2half2_rn(v1.x, v1.y);
        __half2 d = __floats2half2_rn(v1.z, v1.w);
        uint4 o;
        o.x = *(uint32_t*)&a; o.y = *(uint32_t*)&b;
        o.z = *(uint32_t*)&c; o.w = *(uint32_t*)&d;
        dst[i] = o;
    }
}

// ---------------- gating ----------------
__global__ void gate_kernel(const float* __restrict__ x, const float* __restrict__ gw, int T) {
    int warp = (blockIdx.x * blockDim.x + threadIdx.x) >> 5;
    int lane = threadIdx.x & 31;
    if (warp >= T) return;
    const float* xr = x + (size_t)warp * D_MODEL;
    float logit[NE];
#pragma unroll
    for (int e = 0; e < NE; e++) {
        float s = 0.f;
        for (int k = lane; k < D_MODEL; k += 32)
            s = fmaf(xr[k], gw[e * D_MODEL + k], s);
#pragma unroll
        for (int o = 16; o; o >>= 1) s += __shfl_xor_sync(0xffffffffu, s, o);
        logit[e] = s;
    }
    if (lane == 0) {
        int i0 = 0; float v0 = logit[0];
#pragma unroll
        for (int e = 1; e < NE; e++) if (logit[e] > v0) { v0 = logit[e]; i0 = e; }
        int i1 = -1; float v1 = -1e30f;
#pragma unroll
        for (int e = 0; e < NE; e++) if (e != i0 && logit[e] > v1) { v1 = logit[e]; i1 = e; }
        float e1 = expf(v1 - v0);
        float inv = 1.f / (1.f + e1);
        g_topk [2 * warp] = i0;  g_topk [2 * warp + 1] = i1;
        g_gates[2 * warp] = inv; g_gates[2 * warp + 1] = e1 * inv;
    }
}

// ---------------- routing (deterministic prefix scan) ----------------
__global__ void route_kernel(int T) {
    int e = blockIdx.x, tid = threadIdx.x, lane = tid & 31, wid = tid >> 5;
    if (e == NE) {
        for (int i = tid; i < T; i += blockDim.x) {
            g_tok[i] = i; g_rowgate[i] = 1.f; g_rowslot[i] = 0;
        }
        return;
    }
    __shared__ int wsum[8], wpre[8], s_total;
    int base = 0;
    for (int t0 = 0; t0 < T; t0 += 256) {
        int t = t0 + tid, slot = -1;
        if (t < T) {
            if      (g_topk[2 * t]     == e) slot = 0;
            else if (g_topk[2 * t + 1] == e) slot = 1;
        }
        unsigned m = __ballot_sync(0xffffffffu, slot >= 0);
        int pre = __popc(m & ((1u << lane) - 1u));
        if (lane == 0) wsum[wid] = __popc(m);
        __syncthreads();
        if (tid == 0) {
            int a = 0;
            for (int w = 0; w < 8; w++) { wpre[w] = a; a += wsum[w]; }
            s_total = a;
        }
        __syncthreads();
        if (slot >= 0) {
            int pos = base + wpre[wid] + pre;
            size_t r = (size_t)(e + 1) * T_MAX + pos;
            g_tok[r] = t; g_rowgate[r] = g_gates[2 * t + slot];
            g_rowslot[r] = (unsigned char)slot;
        }
        base += s_total;
        __syncthreads();
    }
    if (tid == 0) g_counts[e] = base;
}

// ---------------- fp16 mma.sync GEMM (R6 structure: known-good) ----------
// 128x128 block, 4 warps (2x2) of 64x64, BKH=32 halves/iter, 3-stage cp.async.
// smem tile layout: logical row m (64B = 4 x 16B atoms) packed 2 rows per 128B
// physical row; atom position swizzled: a' = a ^ (prow & 7).
// STAGE1: H = fp16(silu(X @ W1^T)); STAGE2: Y = H @ W2^T (gated).
template <int STAGE, int OUTMODE>
__global__ void __launch_bounds__(128, 2)
gemm_mma(float* __restrict__ out, int T, int zoff) {
    constexpr int K     = (STAGE == 1) ? D_MODEL : HID;
    constexpr int NITER = K / BKH;

    const int s = blockIdx.z + zoff;
    const int count = (s == 0) ? T : g_counts[s - 1];
    const int m0 = blockIdx.y * BM;
    if (m0 >= count) return;
    const int n0 = blockIdx.x * BN;
    const size_t rowbase = (size_t)s * T_MAX;
    const __half* __restrict__ Bw =
        ((STAGE == 1) ? g_W1h : g_W2h) + (size_t)s * K * ((STAGE == 1) ? HID : D_MODEL);
    const __half* __restrict__ Ah = g_Hh + (rowbase + m0) * (size_t)HID;

    extern __shared__ char smem[];
    const uint32_t smb = smem_u32(smem);
    int* stok = (int*)(smem + NSTG * STG_BYTES);

    const int tid = threadIdx.x;
    if (STAGE == 1) {
        for (int i = tid; i < BM; i += 128) {
            int m = m0 + i;
            stok[i] = (m < count) ? g_tok[rowbase + m] : -1;
        }
        __syncthreads();
    }

    // fill buffer buf with k-halves [it*BKH, it*BKH+32): 8 cp.async/thread
    auto fill = [&](int it, int buf) {
        const int kt = it * BKH;
        const uint32_t aB = smb + buf * STG_BYTES;
        const uint32_t bB = aB + 8192;
#pragma unroll
        for (int i = 0; i < 4; i++) {
            int cid = i * 128 + tid;
            int m = cid >> 2, c = cid & 3;
            int prow = m >> 1;
            uint32_t off = prow * 128 + ((((m & 1) * 4 + c) ^ (prow & 7)) << 4);
            const __half* srcA; int zf = 16;
            if (STAGE == 1) {
                int t = stok[m];
                srcA = g_Xh + (size_t)((t < 0) ? 0 : t) * D_MODEL + kt + c * 8;
                if (t < 0) zf = 0;
            } else {
                int mg = m0 + m;
                srcA = Ah + (size_t)((mg < count) ? m : 0) * HID + kt + c * 8;
                if (mg >= count) zf = 0;
            }
            cpa16(aB + off, srcA, zf);
            cpa16(bB + off, Bw + (size_t)(n0 + m) * K + kt + c * 8, 16);
        }
        cpa_commit();
    };

    const int lane = tid & 31, wid = tid >> 5;
    const int g = lane >> 2, t4 = lane & 3;
    const int warpM = (wid & 1) * 64, warpN = (wid >> 1) * 64;

    // per-lane ldmatrix base offsets (mt=0 / np=0, ks=0, stage 0)
    uint32_t aoff, boff;
    {
        int ar = lane & 15, asel = lane >> 4;       // A: row, atom
        int m = warpM + ar, prow = m >> 1;
        int a = (m & 1) * 4 + asel;
        aoff = prow * 128 + ((a ^ (prow & 7)) << 4);
        int br = ((lane >> 4) << 3) + (lane & 7);   // B: row
        int bsel = (lane >> 3) & 1;                 // B: atom
        int n = warpN + br, prow2 = n >> 1;
        int ab = (n & 1) * 4 + bsel;
        boff = 8192 + prow2 * 128 + ((ab ^ (prow2 & 7)) << 4);
    }

    float acc[4][8][4];
#pragma unroll
    for (int a = 0; a < 4; a++)
#pragma unroll
        for (int b = 0; b < 8; b++)
#pragma unroll
            for (int c = 0; c < 4; c++) acc[a][b][c] = 0.f;

    fill(0, 0);
    fill(1, 1);

    for (int it = 0; it < NITER; it++) {
        const int buf = it % NSTG;
        asm volatile("cp.async.wait_group 1;" ::: "memory");
        __syncthreads();
        if (it + 2 < NITER) fill(it + 2, (it + 2) % NSTG);

        const uint32_t Ab = smb + buf * STG_BYTES + aoff;
        const uint32_t Bb = smb + buf * STG_BYTES + boff;
#pragma unroll
        for (int ks = 0; ks < 2; ks++) {
            uint32_t af[4][4], bf[4][4];
#pragma unroll
            for (int mt = 0; mt < 4; mt++)
                LDSM4(af[mt][0], af[mt][1], af[mt][2], af[mt][3],
                      (Ab + mt * 1024) ^ (ks * 32));
#pragma unroll
            for (int np = 0; np < 4; np++)
                LDSM4(bf[np][0], bf[np][1], bf[np][2], bf[np][3],
                      (Bb + np * 1024) ^ (ks * 32));
#pragma unroll
            for (int mt = 0; mt < 4; mt++)
#pragma unroll
                for (int nt = 0; nt < 8; nt++)
                    asm volatile(
                        "mma.sync.aligned.m16n8k16.row.col.f32.f16.f16.f32 "
                        "{%0,%1,%2,%3}, {%4,%5,%6,%7}, {%8,%9}, {%0,%1,%2,%3};"
                        : "+f"(acc[mt][nt][0]), "+f"(acc[mt][nt][1]),
                          "+f"(acc[mt][nt][2]), "+f"(acc[mt][nt][3])
                        : "r"(af[mt][0]), "r"(af[mt][1]), "r"(af[mt][2]), "r"(af[mt][3]),
                          "r"(bf[nt >> 1][(nt & 1) * 2]), "r"(bf[nt >> 1][(nt & 1) * 2 + 1]));
        }
    }

    // ---- epilogue: c0,c1 -> (row g, cols 2t4,2t4+1); c2,c3 -> row g+8
#pragma unroll
    for (int mt = 0; mt < 4; mt++) {
#pragma unroll
        for (int half = 0; half < 2; half++) {
            int m = m0 + warpM + mt * 16 + g + half * 8;
            if (m >= count) continue;
            size_t r = rowbase + m;
            if (STAGE == 1) {
                __half* hp = g_Hh + r * (size_t)HID + n0 + warpN + 2 * t4;
#pragma unroll
                for (int nt = 0; nt < 8; nt++) {
                    float v0 = acc[mt][nt][half * 2 + 0];
                    float v1 = acc[mt][nt][half * 2 + 1];
                    v0 = v0 / (1.f + __expf(-v0));
                    v1 = v1 / (1.f + __expf(-v1));
                    *(__half2*)(hp + nt * 8) = __floats2half2_rn(v0, v1);
                }
            } else {
                int   t  = g_tok[r];
                float gv = g_rowgate[r];
                float* op;
                if (OUTMODE == 0)
                    op = out + (size_t)t * D_MODEL + n0 + warpN + 2 * t4;
                else {
                    int sl = g_rowslot[r];
                    op = g_slotbuf + ((size_t)sl * T_MAX + (size_t)t) * D_MODEL
                       + n0 + warpN + 2 * t4;
                }
#pragma unroll
                for (int nt = 0; nt < 8; nt++)
                    *(float2*)(op + nt * 8) =
                        make_float2(gv * acc[mt][nt][half * 2 + 0],
                                    gv * acc[mt][nt][half * 2 + 1]);
            }
        }
    }
}

// ---------------- combine ----------------
__global__ void combine_kernel(float* __restrict__ out, int T) {
    size_t n = (size_t)T * D_MODEL;
    size_t stride = (size_t)gridDim.x * blockDim.x;
    for (size_t i = (size_t)blockIdx.x * blockDim.x + threadIdx.x; i < n; i += stride)
        out[i] += g_slotbuf[i] + g_slotbuf[(size_t)T_MAX * D_MODEL + i];
}

// ---------------- launch ----------------
extern "C" void kernel_launch(void* const* d_in, const int* in_sizes, int n_in,
                              void* d_out, int out_size) {
    const float* x   = (const float*)d_in[0];
    const float* sw1 = (const float*)d_in[1];
    const float* sw2 = (const float*)d_in[2];
    const float* ew1 = (const float*)d_in[3];
    const float* ew2 = (const float*)d_in[4];
    const float* gw  = (const float*)d_in[5];
    float* out = (float*)d_out;
    int T = in_sizes[0] / D_MODEL;

    cudaFuncSetAttribute(gemm_mma<1, 0>, cudaFuncAttributeMaxDynamicSharedMemorySize, SMEM_BYTES);
    cudaFuncSetAttribute(gemm_mma<2, 0>, cudaFuncAttributeMaxDynamicSharedMemorySize, SMEM_BYTES);
    cudaFuncSetAttribute(gemm_mma<2, 1>, cudaFuncAttributeMaxDynamicSharedMemorySize, SMEM_BYTES);

    __half *d_Xh, *d_W1h, *d_W2h;
    cudaGetSymbolAddress((void**)&d_Xh, g_Xh);
    cudaGetSymbolAddress((void**)&d_W1h, g_W1h);
    cudaGetSymbolAddress((void**)&d_W2h, g_W2h);

    // fp32 -> fp16 RNE conversion; 32B/thread-iter streaming
    to_half_kernel<<<1024, 256>>>((uint4*)d_Xh, (const float4*)x, T * D_MODEL / 8);
    to_half_kernel<<<2048, 256>>>((uint4*)d_W1h, (const float4*)sw1, HID * D_MODEL / 8);
    to_half_kernel<<<16384, 256>>>((uint4*)(d_W1h + (size_t)HID * D_MODEL),
                                   (const float4*)ew1, NE * HID * D_MODEL / 8);
    to_half_kernel<<<2048, 256>>>((uint4*)d_W2h, (const float4*)sw2, D_MODEL * HID / 8);
    to_half_kernel<<<16384, 256>>>((uint4*)(d_W2h + (size_t)D_MODEL * HID),
                                   (const float4*)ew2, NE * D_MODEL * HID / 8);

    gate_kernel<<<(T + 7) / 8, 256>>>(x, gw, T);
    route_kernel<<<NE + 1, 256>>>(T);

    {   // stage 1: all 9 segments (empty m-tiles early-exit)
        dim3 g(HID / BN, T_MAX / BM, NE + 1);
        gemm_mma<1, 0><<<g, 128, SMEM_BYTES>>>(nullptr, T, 0);
    }
    {   // stage 2 shared -> out ('=' writes every element)
        dim3 g(D_MODEL / BN, T_MAX / BM, 1);
        gemm_mma<2, 0><<<g, 128, SMEM_BYTES>>>(out, T, 0);
    }
    {   // stage 2 experts -> per-slot buffers (race-free)
        dim3 g(D_MODEL / BN, T_MAX / BM, NE);
        gemm_mma<2, 1><<<g, 128, SMEM_BYTES>>>(nullptr, T, 1);
    }
    combine_kernel<<<1024, 256>>>(out, T);
}